// round 13
// baseline (speedup 1.0000x reference)
#include <cuda_runtime.h>
#include <cuda_bf16.h>
#include <math.h>

#define N_GAUSS 2048
#define HEIGHT  192
#define WIDTH   192
#define HW      (HEIGHT*WIDTH)
#define ALPHA_MAX 0.999f
#define ALPHA_MIN (1.0f/255.0f)
#define NSEG    16
#define SEG     (N_GAUSS / NSEG)   // 128
#define NGRP    (SEG / 32)         // 4 cull groups per segment

// Depth-sorted gaussian data (80 KB total -> L1/L2 resident)
__device__ float4 g_A[N_GAUSS];  // mx, my, 0.5*conic_a, conic_b
__device__ float4 g_B[N_GAUSS];  // 0.5*conic_c, opacity, col_r, col_g
__device__ float2 g_C[N_GAUSS];  // col_b, pad
__device__ float4 g_D[N_GAUSS];  // mx, my, rx, ry : packed cull record

// ---------------------------------------------------------------------------
// Kernel 1: rank-by-counting sort, one warp per gaussian.
// Order lexicographic (depth, index), ties by index.
// ---------------------------------------------------------------------------
__global__ void __launch_bounds__(256)
sort_scatter_kernel(const float* __restrict__ means2d,
                    const float* __restrict__ conics,
                    const float* __restrict__ colors,
                    const float* __restrict__ opacities,
                    const float* __restrict__ depths)
{
    __shared__ float sd[N_GAUSS];
    const int tid  = threadIdx.x;
    const int warp = tid >> 5, lane = tid & 31;
    const int gid  = blockIdx.x * 8 + warp;

    // Hoisted param loads (lane 0; overlaps staging + count latency).
    float p_mx, p_my, p_ca, p_cb, p_cc, p_op, p_cr, p_cg, p_cbl;
    if (lane == 0) {
        p_mx = means2d[2*gid + 0];
        p_my = means2d[2*gid + 1];
        p_ca = conics[3*gid + 0];
        p_cb = conics[3*gid + 1];
        p_cc = conics[3*gid + 2];
        p_op = opacities[gid];
        p_cr = colors[3*gid + 0];
        p_cg = colors[3*gid + 1];
        p_cbl= colors[3*gid + 2];
    }

    #pragma unroll
    for (int i = tid; i < N_GAUSS; i += 256)
        sd[i] = depths[i];
    __syncthreads();

    const float myd = sd[gid];
    int c = 0;
    #pragma unroll 16
    for (int k = 0; k < N_GAUSS / 32; ++k) {
        int i = k * 32 + lane;
        float d = sd[i];
        c += (d < myd) || ((d == myd) && (i < gid));
    }
    int rank = __reduce_add_sync(0xffffffffu, c);

    if (lane == 0) {
        // alpha >= 1/255 <=> sigma <= log(255*op); margin keeps the AABB
        // cull conservative vs the exact in-walk gate.
        float t = logf(255.0f * p_op) + 1e-4f;
        float det = p_ca * p_cc - p_cb * p_cb;
        float inv = 2.0f * fmaxf(t, 0.0f) / det;
        float rx = sqrtf(fmaxf(inv * p_cc, 0.0f)) + 1e-3f;
        float ry = sqrtf(fmaxf(inv * p_ca, 0.0f)) + 1e-3f;
        g_A[rank] = make_float4(p_mx, p_my, 0.5f * p_ca, p_cb);
        g_B[rank] = make_float4(0.5f * p_cc, p_op, p_cr, p_cg);
        g_C[rank] = make_float2(p_cbl, 0.0f);
        g_D[rank] = make_float4(p_mx, p_my, rx, ry);
    }
}

// ---------------------------------------------------------------------------
// Kernel 2 (fused render + combine): 8x8 px tile per block, 512 threads =
// 16 warps = 16 depth segments x 1 warp. Each warp covers the WHOLE tile
// with 2 px/thread (two independent per-pixel chains = double ILP), so a
// gaussian is walked by ~16 tile-warps instead of ~28 narrow strips.
// Phase-split: all 4 cull ballots first (overlapped LDG.128s), then the
// exact in-order 2-wide survivor walk. Fold in smem after one barrier.
// ---------------------------------------------------------------------------
__global__ void __launch_bounds__(512)
render_fused_kernel(const float* __restrict__ background, float* __restrict__ out)
{
    __shared__ float4 smP[NSEG][64];   // (accR, accG, accB, T_seg) per pixel

    const int tid  = threadIdx.x;
    const int seg  = tid >> 5;           // 0..15 : warp == segment
    const int lane = tid & 31;
    const int base = seg * SEG;

    const int tx0 = blockIdx.x * 8;
    const int ty0 = blockIdx.y * 8;
    const int xl  = lane & 7;            // 0..7
    const int yl0 = lane >> 3;           // 0..3
    const int yl1 = yl0 + 4;             // 4..7
    const float px  = (float)(tx0 + xl) + 0.5f;
    const float py0 = (float)(ty0 + yl0) + 0.5f;
    const float py1 = (float)(ty0 + yl1) + 0.5f;

    // Whole-tile pixel-center bounds (cull granularity = tile).
    const float sxmin = tx0 + 0.5f;
    const float sxmax = tx0 + 7.5f;
    const float symin = ty0 + 0.5f;
    const float symax = ty0 + 7.5f;

    // Phase 1: independent cull burst — all group ballots up front.
    unsigned masks[NGRP];
    #pragma unroll
    for (int k = 0; k < NGRP; ++k) {
        float4 d = g_D[base + k * 32 + lane];
        bool pred = (d.x - d.z <= sxmax) & (d.x + d.z >= sxmin) &
                    (d.y - d.w <= symax) & (d.y + d.w >= symin);
        masks[k] = __ballot_sync(0xffffffffu, pred);
    }

    // Phase 2: exact, in-order, 2-wide survivor walk; 2 pixels per thread.
    float T0 = 1.0f, T1 = 1.0f;
    float r0 = 0.0f, g0 = 0.0f, b0 = 0.0f;
    float r1 = 0.0f, g1 = 0.0f, b1 = 0.0f;

    #pragma unroll
    for (int k = 0; k < NGRP; ++k) {
        unsigned mask = masks[k];
        const int gbase = base + k * 32;
        while (mask) {
            int j0 = gbase + (__ffs(mask) - 1);
            mask &= mask - 1;
            bool two = (mask != 0);
            int j1 = two ? (gbase + (__ffs(mask) - 1)) : j0;
            if (two) mask &= mask - 1;

            float4 A0 = g_A[j0], A1 = g_A[j1];
            float4 B0 = g_B[j0], B1 = g_B[j1];
            float2 C0 = g_C[j0], C1 = g_C[j1];

            // survivor 0, both pixels (dx shared)
            float dx0 = px - A0.x;
            float dxa = A0.z * dx0 * dx0;            // 0.5a*dx^2
            float dya0 = py0 - A0.y, dya1 = py1 - A0.y;
            float s00 = dxa + B0.x * dya0 * dya0 + A0.w * dx0 * dya0;
            float s01 = dxa + B0.x * dya1 * dya1 + A0.w * dx0 * dya1;
            // survivor 1, both pixels
            float dx1 = px - A1.x;
            float dxb = A1.z * dx1 * dx1;
            float dyb0 = py0 - A1.y, dyb1 = py1 - A1.y;
            float s10 = dxb + B1.x * dyb0 * dyb0 + A1.w * dx1 * dyb0;
            float s11 = dxb + B1.x * dyb1 * dyb1 + A1.w * dx1 * dyb1;

            float e00 = __expf(-s00), e01 = __expf(-s01);
            float e10 = __expf(-s10), e11 = __expf(-s11);

            float a00 = fminf(ALPHA_MAX, B0.y * e00);
            float a01 = fminf(ALPHA_MAX, B0.y * e01);
            float a10 = fminf(ALPHA_MAX, B1.y * e10);
            float a11 = fminf(ALPHA_MAX, B1.y * e11);
            // exact reference gate as selects
            a00 = ((s00 > 0.0f) & (a00 >= ALPHA_MIN)) ? a00 : 0.0f;
            a01 = ((s01 > 0.0f) & (a01 >= ALPHA_MIN)) ? a01 : 0.0f;
            a10 = ((s10 > 0.0f) & (a10 >= ALPHA_MIN) & two) ? a10 : 0.0f;
            a11 = ((s11 > 0.0f) & (a11 >= ALPHA_MIN) & two) ? a11 : 0.0f;

            // pixel0 chain (in depth order: survivor0 then survivor1)
            float w = T0 * a00;
            r0 = fmaf(w, B0.z, r0); g0 = fmaf(w, B0.w, g0); b0 = fmaf(w, C0.x, b0);
            T0 *= (1.0f - a00);
            w = T0 * a10;
            r0 = fmaf(w, B1.z, r0); g0 = fmaf(w, B1.w, g0); b0 = fmaf(w, C1.x, b0);
            T0 *= (1.0f - a10);
            // pixel1 chain (independent of pixel0 -> ILP)
            w = T1 * a01;
            r1 = fmaf(w, B0.z, r1); g1 = fmaf(w, B0.w, g1); b1 = fmaf(w, C0.x, b1);
            T1 *= (1.0f - a01);
            w = T1 * a11;
            r1 = fmaf(w, B1.z, r1); g1 = fmaf(w, B1.w, g1); b1 = fmaf(w, C1.x, b1);
            T1 *= (1.0f - a11);
        }
    }

    smP[seg][yl0 * 8 + xl] = make_float4(r0, g0, b0, T0);
    smP[seg][yl1 * 8 + xl] = make_float4(r1, g1, b1, T1);
    __syncthreads();

    // Fold the 16 segments front-to-back + background (threads 0..63).
    if (tid < 64) {
        float fr = 0.0f, fg = 0.0f, fb = 0.0f, fT = 1.0f;
        #pragma unroll
        for (int s = 0; s < NSEG; ++s) {
            float4 v = smP[s][tid];
            fr = fmaf(fT, v.x, fr);
            fg = fmaf(fT, v.y, fg);
            fb = fmaf(fT, v.z, fb);
            fT *= v.w;
        }
        const int pix = (ty0 + (tid >> 3)) * WIDTH + tx0 + (tid & 7);
        out[0 * HW + pix] = fmaf(background[0], fT, fr);
        out[1 * HW + pix] = fmaf(background[1], fT, fg);
        out[2 * HW + pix] = fmaf(background[2], fT, fb);
    }
}

// ---------------------------------------------------------------------------
extern "C" void kernel_launch(void* const* d_in, const int* in_sizes, int n_in,
                              void* d_out, int out_size)
{
    const float* means2d    = (const float*)d_in[0];
    const float* conics     = (const float*)d_in[1];
    const float* colors     = (const float*)d_in[2];
    const float* opacities  = (const float*)d_in[3];
    const float* depths     = (const float*)d_in[4];
    const float* background = (const float*)d_in[5];
    float* out = (float*)d_out;

    sort_scatter_kernel<<<N_GAUSS / 8, 256>>>(means2d, conics, colors, opacities, depths);
    dim3 grid(WIDTH / 8, HEIGHT / 8);
    render_fused_kernel<<<grid, 512>>>(background, out);
}

// round 14
// speedup vs baseline: 1.0306x; 1.0306x over previous
#include <cuda_runtime.h>
#include <cuda_bf16.h>
#include <math.h>

#define N_GAUSS 2048
#define HEIGHT  192
#define WIDTH   192
#define HW      (HEIGHT*WIDTH)
#define ALPHA_MAX 0.999f
#define ALPHA_MIN (1.0f/255.0f)
#define NSEG    16
#define SEG     (N_GAUSS / NSEG)   // 128
#define NGRP    (SEG / 32)         // 4 cull groups per segment
#define TILE_W  16
#define TILE_H  8
#define TPX     128                 // pixels per tile

// Depth-sorted gaussian data (80 KB total -> L1/L2 resident)
__device__ float4 g_A[N_GAUSS];  // mx, my, 0.5*conic_a, conic_b
__device__ float4 g_B[N_GAUSS];  // 0.5*conic_c, opacity, col_r, col_g
__device__ float2 g_C[N_GAUSS];  // col_b, pad
__device__ float4 g_D[N_GAUSS];  // mx, my, rx, ry : packed cull record

// ---------------------------------------------------------------------------
// Kernel 1: rank-by-counting sort, one warp per gaussian, SINGLE WAVE:
// 128 blocks x 512 threads (16 warps = 16 gaussians per block).
// Order lexicographic (depth, index), ties by index.
// ---------------------------------------------------------------------------
__global__ void __launch_bounds__(512)
sort_scatter_kernel(const float* __restrict__ means2d,
                    const float* __restrict__ conics,
                    const float* __restrict__ colors,
                    const float* __restrict__ opacities,
                    const float* __restrict__ depths)
{
    __shared__ float sd[N_GAUSS];
    const int tid  = threadIdx.x;
    const int warp = tid >> 5, lane = tid & 31;
    const int gid  = blockIdx.x * 16 + warp;

    // Hoisted param loads (lane 0; overlaps staging + count latency).
    float p_mx, p_my, p_ca, p_cb, p_cc, p_op, p_cr, p_cg, p_cbl;
    if (lane == 0) {
        p_mx = means2d[2*gid + 0];
        p_my = means2d[2*gid + 1];
        p_ca = conics[3*gid + 0];
        p_cb = conics[3*gid + 1];
        p_cc = conics[3*gid + 2];
        p_op = opacities[gid];
        p_cr = colors[3*gid + 0];
        p_cg = colors[3*gid + 1];
        p_cbl= colors[3*gid + 2];
    }

    #pragma unroll
    for (int i = tid; i < N_GAUSS; i += 512)
        sd[i] = depths[i];
    __syncthreads();

    const float myd = sd[gid];
    int c = 0;
    #pragma unroll 16
    for (int k = 0; k < N_GAUSS / 32; ++k) {
        int i = k * 32 + lane;
        float d = sd[i];
        c += (d < myd) || ((d == myd) && (i < gid));
    }
    int rank = __reduce_add_sync(0xffffffffu, c);

    if (lane == 0) {
        // alpha >= 1/255 <=> sigma <= log(255*op); margin keeps the AABB
        // cull conservative vs the exact in-walk gate.
        float t = logf(255.0f * p_op) + 1e-4f;
        float det = p_ca * p_cc - p_cb * p_cb;
        float inv = 2.0f * fmaxf(t, 0.0f) / det;
        float rx = sqrtf(fmaxf(inv * p_cc, 0.0f)) + 1e-3f;
        float ry = sqrtf(fmaxf(inv * p_ca, 0.0f)) + 1e-3f;
        g_A[rank] = make_float4(p_mx, p_my, 0.5f * p_ca, p_cb);
        g_B[rank] = make_float4(0.5f * p_cc, p_op, p_cr, p_cg);
        g_C[rank] = make_float2(p_cbl, 0.0f);
        g_D[rank] = make_float4(p_mx, p_my, rx, ry);
    }
}

// ---------------------------------------------------------------------------
// Kernel 2 (fused render + combine): 16x8 px tile per block, 512 threads =
// 16 warps = 16 depth segments. Each warp covers the whole tile with
// 4 px/thread (four independent composite chains = ILP). A gaussian is
// walked by ~11 tiles instead of ~18 (8x8) or ~28 (8x4 strips).
// Phase-split cull (4 overlapped LDG.128 ballots), exact in-order 2-wide
// survivor walk, smem fold after one barrier.
// ---------------------------------------------------------------------------
__global__ void __launch_bounds__(512, 2)
render_fused_kernel(const float* __restrict__ background, float* __restrict__ out)
{
    __shared__ float4 smP[NSEG][TPX];  // (accR, accG, accB, T_seg) per pixel

    const int tid  = threadIdx.x;
    const int seg  = tid >> 5;           // 0..15 : warp == segment
    const int lane = tid & 31;
    const int base = seg * SEG;

    const int tx0 = blockIdx.x * TILE_W;
    const int ty0 = blockIdx.y * TILE_H;
    const int xl  = lane & 15;           // 0..15
    const int yb  = (lane >> 4) * 4;     // 0 or 4
    const float px  = (float)(tx0 + xl) + 0.5f;
    const float pyb = (float)(ty0 + yb) + 0.5f;  // rows yb..yb+3

    // Whole-tile pixel-center bounds (cull granularity = tile).
    const float sxmin = tx0 + 0.5f;
    const float sxmax = tx0 + TILE_W - 0.5f;
    const float symin = ty0 + 0.5f;
    const float symax = ty0 + TILE_H - 0.5f;

    // Phase 1: independent cull burst — all group ballots up front.
    unsigned masks[NGRP];
    #pragma unroll
    for (int k = 0; k < NGRP; ++k) {
        float4 d = g_D[base + k * 32 + lane];
        bool pred = (d.x - d.z <= sxmax) & (d.x + d.z >= sxmin) &
                    (d.y - d.w <= symax) & (d.y + d.w >= symin);
        masks[k] = __ballot_sync(0xffffffffu, pred);
    }

    // Phase 2: exact, in-order, 2-wide survivor walk; 4 pixels per thread.
    float T[4]  = {1.0f, 1.0f, 1.0f, 1.0f};
    float ar[4] = {0,0,0,0}, ag[4] = {0,0,0,0}, ab[4] = {0,0,0,0};

    #pragma unroll
    for (int k = 0; k < NGRP; ++k) {
        unsigned mask = masks[k];
        const int gbase = base + k * 32;
        while (mask) {
            int j0 = gbase + (__ffs(mask) - 1);
            mask &= mask - 1;
            bool two = (mask != 0);
            int j1 = two ? (gbase + (__ffs(mask) - 1)) : j0;
            if (two) mask &= mask - 1;

            float4 A0 = g_A[j0], A1 = g_A[j1];
            float4 B0 = g_B[j0], B1 = g_B[j1];
            float2 C0 = g_C[j0], C1 = g_C[j1];

            // dx terms shared across the 4 rows.
            float dx0 = px - A0.x;
            float qa0 = A0.z * dx0 * dx0;     // 0.5a*dx^2
            float bx0 = A0.w * dx0;           // b*dx
            float dx1 = px - A1.x;
            float qa1 = A1.z * dx1 * dx1;
            float bx1 = A1.w * dx1;

            #pragma unroll
            for (int r = 0; r < 4; ++r) {
                float py = pyb + (float)r;
                float dy0 = py - A0.y;
                float dy1 = py - A1.y;
                float s0 = qa0 + (B0.x * dy0 + bx0) * dy0;  // 0.5a dx^2 + 0.5c dy^2 + b dx dy
                float s1 = qa1 + (B1.x * dy1 + bx1) * dy1;
                float e0 = __expf(-s0);
                float e1 = __expf(-s1);
                float a0 = fminf(ALPHA_MAX, B0.y * e0);
                float a1 = fminf(ALPHA_MAX, B1.y * e1);
                // exact reference gate as selects
                a0 = ((s0 > 0.0f) & (a0 >= ALPHA_MIN)) ? a0 : 0.0f;
                a1 = ((s1 > 0.0f) & (a1 >= ALPHA_MIN) & two) ? a1 : 0.0f;

                float w = T[r] * a0;
                ar[r] = fmaf(w, B0.z, ar[r]);
                ag[r] = fmaf(w, B0.w, ag[r]);
                ab[r] = fmaf(w, C0.x, ab[r]);
                T[r] *= (1.0f - a0);
                w = T[r] * a1;
                ar[r] = fmaf(w, B1.z, ar[r]);
                ag[r] = fmaf(w, B1.w, ag[r]);
                ab[r] = fmaf(w, C1.x, ab[r]);
                T[r] *= (1.0f - a1);
            }
        }
    }

    #pragma unroll
    for (int r = 0; r < 4; ++r)
        smP[seg][(yb + r) * TILE_W + xl] = make_float4(ar[r], ag[r], ab[r], T[r]);
    __syncthreads();

    // Fold the 16 segments front-to-back + background (threads 0..127).
    if (tid < TPX) {
        float fr = 0.0f, fg = 0.0f, fb = 0.0f, fT = 1.0f;
        #pragma unroll
        for (int s = 0; s < NSEG; ++s) {
            float4 v = smP[s][tid];
            fr = fmaf(fT, v.x, fr);
            fg = fmaf(fT, v.y, fg);
            fb = fmaf(fT, v.z, fb);
            fT *= v.w;
        }
        const int pix = (ty0 + (tid >> 4)) * WIDTH + tx0 + (tid & 15);
        out[0 * HW + pix] = fmaf(background[0], fT, fr);
        out[1 * HW + pix] = fmaf(background[1], fT, fg);
        out[2 * HW + pix] = fmaf(background[2], fT, fb);
    }
}

// ---------------------------------------------------------------------------
extern "C" void kernel_launch(void* const* d_in, const int* in_sizes, int n_in,
                              void* d_out, int out_size)
{
    const float* means2d    = (const float*)d_in[0];
    const float* conics     = (const float*)d_in[1];
    const float* colors     = (const float*)d_in[2];
    const float* opacities  = (const float*)d_in[3];
    const float* depths     = (const float*)d_in[4];
    const float* background = (const float*)d_in[5];
    float* out = (float*)d_out;

    sort_scatter_kernel<<<N_GAUSS / 16, 512>>>(means2d, conics, colors, opacities, depths);
    dim3 grid(WIDTH / TILE_W, HEIGHT / TILE_H);
    render_fused_kernel<<<grid, 512>>>(background, out);
}